// round 6
// baseline (speedup 1.0000x reference)
#include <cuda_runtime.h>
#include <cuda_fp16.h>
#include <math.h>

#define NN 50000
#define FF 48
#define CC 16     // H*C1 with H=1 -> softmax == 1, attention vanishes
#define L1 8
#define EMAXV 1700000

// ---------------- device scratch ----------------
__device__ __align__(32) __half g_yh[NN * CC];    // x @ W  (fp16)
__device__ __align__(32) __half g_aggh[NN * CC];  // fp16 segment sum (self loop preloaded)
__device__ int   g_degi[NN];                      // in-degree + 1 (self loop)
__device__ int   g_src32[EMAXV];                  // int32 src ids
__device__ int   g_dst32[EMAXV];                  // int32 dst ids
__device__ int   g_is64;

// ---------------- detect edge dtype + init deg + zero loss slot ----------------
// int64 node ids < 50000 => every odd 32-bit word of the first 1024 entries is 0.
__global__ void k_detect(const unsigned* __restrict__ ew, float* losss, int n) {
    int i = blockIdx.x * blockDim.x + threadIdx.x;
    if (i < n) g_degi[i] = 1;                 // self loop
    if (blockIdx.x == 0) {
        __shared__ unsigned any;
        if (threadIdx.x == 0) any = 0u;
        __syncthreads();
        unsigned v = 0u;
        for (int k = threadIdx.x; k < 1024; k += blockDim.x) v |= ew[2 * k + 1];
        if (v) atomicOr(&any, 1u);
        __syncthreads();
        if (threadIdx.x == 0) {
            g_is64 = (any == 0u) ? 1 : 0;
            if (losss) *losss = 0.0f;
        }
    }
}

// ---------------- fused grid: proj | dst hist+convert | src convert ----------------
__global__ void k_proj_hist(const float* __restrict__ x, const float* __restrict__ W,
                            const void* __restrict__ ei, int n, int E,
                            int projBlocks, int histBlocks) {
    int bx = blockIdx.x;
    if (bx < projBlocks) {
        // ---- projection y = x @ W (smem-staged) ----
        __shared__ float sW[FF * CC];   // 3 KB
        __shared__ float sX[16 * FF];   // 3 KB
        for (int i = threadIdx.x; i < FF * CC; i += blockDim.x) sW[i] = W[i];
        int nodeBase = bx * 16;
        for (int i = threadIdx.x; i < 16 * FF; i += blockDim.x) {
            int g = nodeBase * FF + i;
            sX[i] = (g < n * FF) ? x[g] : 0.0f;
        }
        __syncthreads();
        int node = nodeBase + (threadIdx.x >> 4);
        int c    = threadIdx.x & 15;
        if (node >= n) return;
        const float* xr = &sX[(threadIdx.x >> 4) * FF];
        float acc = 0.0f;
#pragma unroll
        for (int k = 0; k < FF; k++) acc = fmaf(xr[k], sW[k * CC + c], acc);
        __half hv = __float2half(acc);
        g_yh[node * CC + c]   = hv;
        g_aggh[node * CC + c] = hv;     // self-loop contribution
    } else if (bx < projBlocks + histBlocks) {
        // ---- dst: histogram + int32 convert ----
        int b = bx - projBlocks;
        int base = b * 1024;            // 4 edges per thread
        if (g_is64) {
            const long long* dl = (const long long*)ei + E;
#pragma unroll
            for (int k = 0; k < 4; k++) {
                int e = base + k * 256 + threadIdx.x;
                if (e < E) {
                    int d = (int)__ldg(&dl[e]);
                    g_dst32[e] = d;
                    atomicAdd(&g_degi[d], 1);
                }
            }
        } else {
            const int* dl = (const int*)ei + E;
#pragma unroll
            for (int k = 0; k < 4; k++) {
                int e = base + k * 256 + threadIdx.x;
                if (e < E) {
                    int d = __ldg(&dl[e]);
                    g_dst32[e] = d;
                    atomicAdd(&g_degi[d], 1);
                }
            }
        }
    } else {
        // ---- src: int32 convert ----
        int b = bx - projBlocks - histBlocks;
        int base = b * 1024;
        if (g_is64) {
            const long long* sl = (const long long*)ei;
#pragma unroll
            for (int k = 0; k < 4; k++) {
                int e = base + k * 256 + threadIdx.x;
                if (e < E) g_src32[e] = (int)__ldg(&sl[e]);
            }
        } else {
            const int* sl = (const int*)ei;
#pragma unroll
            for (int k = 0; k < 4; k++) {
                int e = base + k * 256 + threadIdx.x;
                if (e < E) g_src32[e] = __ldg(&sl[e]);
            }
        }
    }
}

// ---------------- edge scatter, 2 lanes per edge, fp16 vector RED ----------------
__device__ __forceinline__ void red_h8(__half* addr, uint4 v) {
    asm volatile("red.global.add.noftz.v4.f16x2 [%0], {%1,%2,%3,%4};"
                 :: "l"(addr), "r"(v.x), "r"(v.y), "r"(v.z), "r"(v.w) : "memory");
}

__global__ void k_edge(int E) {
    int t = blockIdx.x * blockDim.x + threadIdx.x;
    int e = t >> 1;            // edge id
    int q = t & 1;             // which 16B half-row
    if (e >= E) return;
    int src = __ldg(&g_src32[e]);
    int dst = __ldg(&g_dst32[e]);
    uint4 v = __ldg((const uint4*)&g_yh[src * CC + q * 8]);
    red_h8(&g_aggh[dst * CC + q * 8], v);
}

// ---------------- head: 2 lanes per node ----------------
__global__ void k_head(const float* __restrict__ bias,
                       const float* __restrict__ l1w,  // [16,8]
                       const float* __restrict__ l1b,
                       const float* __restrict__ ow,   // [8,1]
                       const float* __restrict__ ob,
                       const float* __restrict__ labels,
                       const float* __restrict__ wts,
                       float* __restrict__ pout, float* losss,
                       int n, float inv_n) {
    __shared__ float sb[CC], sl1w[CC * L1], sl1b[L1], sow[L1], sob;
    if (threadIdx.x < CC) sb[threadIdx.x] = bias[threadIdx.x];
    if (threadIdx.x < CC * L1) sl1w[threadIdx.x] = l1w[threadIdx.x];
    if (threadIdx.x < L1) { sl1b[threadIdx.x] = l1b[threadIdx.x]; sow[threadIdx.x] = ow[threadIdx.x]; }
    if (threadIdx.x == 0) sob = ob[0];
    __syncthreads();

    int t = blockIdx.x * blockDim.x + threadIdx.x;
    int i = t >> 1;            // node
    int a = t & 1;             // which 8-channel half
    float term = 0.0f;
    if (i < n) {
        float invdeg = 1.0f / (float)__ldg(&g_degi[i]);
        uint4 r = *(const uint4*)&g_aggh[i * CC + a * 8];
        float h[8];
        {
            const unsigned rr[4] = {r.x, r.y, r.z, r.w};
#pragma unroll
            for (int k = 0; k < 4; k++) {
                float2 f = __half22float2(*(const __half2*)&rr[k]);
                h[2 * k]     = f.x;
                h[2 * k + 1] = f.y;
            }
        }
        int cbase = a * 8;
#pragma unroll
        for (int k = 0; k < 8; k++)
            h[k] = fmaxf(fmaf(h[k], invdeg, sb[cbase + k]), 0.0f);

        // partial MLP over this lane's 8 channels
        float s[L1];
#pragma unroll
        for (int j = 0; j < L1; j++) {
            float acc = 0.0f;
#pragma unroll
            for (int k = 0; k < 8; k++)
                acc = fmaf(h[k], sl1w[(cbase + k) * L1 + j], acc);
            s[j] = acc;
        }
        float z = 0.0f;
#pragma unroll
        for (int j = 0; j < L1; j++) {
            float sj = s[j] + __shfl_xor_sync(0xFFFFFFFFu, s[j], 1);
            float h2 = fmaxf(sj + sl1b[j], 0.0f);
            z = fmaf(h2, sow[j], z);
        }
        if (a == 0) {
            z += sob;
            float p = 1.0f / (1.0f + __expf(-z));
            pout[i] = p;
            const float eps = 1e-7f;
            float pc = fminf(fmaxf(p, eps), 1.0f - eps);
            float sel = (labels[i] > 0.5f) ? pc : (1.0f - pc);  // labels exactly 0/1
            term = wts[i] * (-__logf(sel)) * inv_n;
        }
    }
    // block reduce
#pragma unroll
    for (int off = 16; off > 0; off >>= 1)
        term += __shfl_down_sync(0xFFFFFFFFu, term, off);
    __shared__ float wsum[8];
    int wid = threadIdx.x >> 5, lid = threadIdx.x & 31;
    if (lid == 0) wsum[wid] = term;
    __syncthreads();
    if (threadIdx.x == 0 && losss) {
        float sum = 0.0f;
#pragma unroll
        for (int k = 0; k < (int)(blockDim.x >> 5); k++) sum += wsum[k];
        atomicAdd(losss, sum);
    }
}

// ---------------- launch ----------------
extern "C" void kernel_launch(void* const* d_in, const int* in_sizes, int n_in,
                              void* d_out, int out_size) {
    const float* x      = (const float*)d_in[0];
    const void*  ei     = d_in[1];
    const float* labels = (const float*)d_in[2];
    const float* wts    = (const float*)d_in[3];
    const float* W      = (const float*)d_in[4];
    // d_in[5]=u, d_in[6]=c unused (H=1 softmax == 1)
    const float* bias   = (const float*)d_in[7];
    const float* l1w    = (const float*)d_in[8];
    const float* l1b    = (const float*)d_in[9];
    const float* ow     = (const float*)d_in[10];
    const float* ob     = (const float*)d_in[11];

    int n = in_sizes[0] / FF;
    int E = in_sizes[1] / 2;

    float* out = (float*)d_out;
    int loss_slot = (out_size == n + 1) ? 1 : 0;
    float* pout  = loss_slot ? (out + 1) : out;
    float* losss = loss_slot ? out : (float*)0;

    int projBlocks = (n + 15) / 16;
    int histBlocks = (E + 1023) / 1024;

    k_detect<<<(n + 255) / 256, 256>>>((const unsigned*)ei, losss, n);
    k_proj_hist<<<projBlocks + 2 * histBlocks, 256>>>(x, W, ei, n, E,
                                                      projBlocks, histBlocks);
    long long threads = (long long)E * 2;
    k_edge<<<(int)((threads + 511) / 512), 512>>>(E);
    k_head<<<(n * 2 + 255) / 256, 256>>>(bias, l1w, l1b, ow, ob, labels, wts,
                                         pout, losss, n, 1.0f / (float)n);
}

// round 7
// speedup vs baseline: 1.0150x; 1.0150x over previous
#include <cuda_runtime.h>
#include <cuda_fp16.h>
#include <math.h>

#define NN 50000
#define FF 48
#define CC 16     // H*C1 with H=1 -> softmax == 1, attention vanishes
#define L1 8

// ---------------- device scratch ----------------
__device__ __align__(32) __half g_yh[NN * CC];    // x @ W (fp16)
__device__ __align__(32) __half g_aggh[NN * CC];  // fp16 segment sum (self loop preloaded)
__device__ int g_degi[NN];   // in-degree count; zeroed at module load, re-zeroed by k_head

// int64 node ids < 50000 => odd 32-bit words are all zero. Check the first 8
// entries (identical loads for every thread -> consistent global decision;
// int32 false-positive prob = (1/50000)^8 ~ 0).
__device__ __forceinline__ bool detect64(const unsigned* __restrict__ ew) {
    unsigned v = 0u;
#pragma unroll
    for (int k = 0; k < 8; k++) v |= __ldg(&ew[2 * k + 1]);
    return v == 0u;
}

// ---------------- fused grid: proj | dst histogram ----------------
__global__ void k_proj_hist(const float* __restrict__ x, const float* __restrict__ W,
                            const void* __restrict__ ei, float* losss,
                            int n, int E, int projBlocks) {
    int bx = blockIdx.x;
    if (bx < projBlocks) {
        // ---- projection y = x @ W (smem-staged) ----
        __shared__ float sW[FF * CC];   // 3 KB
        __shared__ float sX[16 * FF];   // 3 KB
        if (bx == 0 && threadIdx.x == 0 && losss) *losss = 0.0f;
        for (int i = threadIdx.x; i < FF * CC; i += blockDim.x) sW[i] = W[i];
        int nodeBase = bx * 16;
        for (int i = threadIdx.x; i < 16 * FF; i += blockDim.x) {
            int g = nodeBase * FF + i;
            sX[i] = (g < n * FF) ? x[g] : 0.0f;
        }
        __syncthreads();
        int node = nodeBase + (threadIdx.x >> 4);
        int c    = threadIdx.x & 15;
        if (node >= n) return;
        const float* xr = &sX[(threadIdx.x >> 4) * FF];
        float acc = 0.0f;
#pragma unroll
        for (int k = 0; k < FF; k++) acc = fmaf(xr[k], sW[k * CC + c], acc);
        __half hv = __float2half(acc);
        g_yh[node * CC + c]   = hv;
        g_aggh[node * CC + c] = hv;     // self-loop contribution
    } else {
        // ---- dst in-degree histogram (g_degi starts at 0 each replay) ----
        int b = bx - projBlocks;
        int base = b * 1024;            // 4 edges per thread
        if (detect64((const unsigned*)ei)) {
            const long long* dl = (const long long*)ei + E;
#pragma unroll
            for (int k = 0; k < 4; k++) {
                int e = base + k * 256 + threadIdx.x;
                if (e < E) atomicAdd(&g_degi[(int)__ldg(&dl[e])], 1);
            }
        } else {
            const int* dl = (const int*)ei + E;
#pragma unroll
            for (int k = 0; k < 4; k++) {
                int e = base + k * 256 + threadIdx.x;
                if (e < E) atomicAdd(&g_degi[__ldg(&dl[e])], 1);
            }
        }
    }
}

// ---------------- edge scatter: 2 lanes/edge, 4 edges/thread (MLP=6+) ----------------
__device__ __forceinline__ void red_h8(__half* addr, uint4 v) {
    asm volatile("red.global.add.noftz.v4.f16x2 [%0], {%1,%2,%3,%4};"
                 :: "l"(addr), "r"(v.x), "r"(v.y), "r"(v.z), "r"(v.w) : "memory");
}

__global__ void k_edge(const void* __restrict__ ei, int E, int Eq) {
    int t = blockIdx.x * blockDim.x + threadIdx.x;
    int i = t >> 1;          // base edge within first quarter
    int q = t & 1;           // which 16B half-row
    if (i >= Eq) return;
    int e0 = i, e1 = i + Eq, e2 = i + 2 * Eq, e3 = i + 3 * Eq;
    bool b1 = e1 < E, b2 = e2 < E, b3 = e3 < E;

    int s0, s1 = 0, s2 = 0, s3 = 0, d0, d1 = 0, d2 = 0, d3 = 0;
    if (detect64((const unsigned*)ei)) {
        const long long* sp = (const long long*)ei;
        const long long* dp = sp + E;
        s0 = (int)__ldg(&sp[e0]);            d0 = (int)__ldg(&dp[e0]);
        if (b1) { s1 = (int)__ldg(&sp[e1]);  d1 = (int)__ldg(&dp[e1]); }
        if (b2) { s2 = (int)__ldg(&sp[e2]);  d2 = (int)__ldg(&dp[e2]); }
        if (b3) { s3 = (int)__ldg(&sp[e3]);  d3 = (int)__ldg(&dp[e3]); }
    } else {
        const int* sp = (const int*)ei;
        const int* dp = sp + E;
        s0 = __ldg(&sp[e0]);            d0 = __ldg(&dp[e0]);
        if (b1) { s1 = __ldg(&sp[e1]);  d1 = __ldg(&dp[e1]); }
        if (b2) { s2 = __ldg(&sp[e2]);  d2 = __ldg(&dp[e2]); }
        if (b3) { s3 = __ldg(&sp[e3]);  d3 = __ldg(&dp[e3]); }
    }
    int qo = q * 8;
    // front-batch the y loads (independent -> high MLP)
    uint4 y0 = __ldg((const uint4*)&g_yh[s0 * CC + qo]);
    uint4 y1 = __ldg((const uint4*)&g_yh[s1 * CC + qo]);
    uint4 y2 = __ldg((const uint4*)&g_yh[s2 * CC + qo]);
    uint4 y3 = __ldg((const uint4*)&g_yh[s3 * CC + qo]);
    red_h8(&g_aggh[d0 * CC + qo], y0);
    if (b1) red_h8(&g_aggh[d1 * CC + qo], y1);
    if (b2) red_h8(&g_aggh[d2 * CC + qo], y2);
    if (b3) red_h8(&g_aggh[d3 * CC + qo], y3);
}

// ---------------- head: 2 lanes per node; self-cleans g_degi ----------------
__global__ void k_head(const float* __restrict__ bias,
                       const float* __restrict__ l1w,  // [16,8]
                       const float* __restrict__ l1b,
                       const float* __restrict__ ow,   // [8,1]
                       const float* __restrict__ ob,
                       const float* __restrict__ labels,
                       const float* __restrict__ wts,
                       float* __restrict__ pout, float* losss,
                       int n, float inv_n) {
    __shared__ float sb[CC], sl1w[CC * L1], sl1b[L1], sow[L1], sob;
    if (threadIdx.x < CC) sb[threadIdx.x] = bias[threadIdx.x];
    if (threadIdx.x < CC * L1) sl1w[threadIdx.x] = l1w[threadIdx.x];
    if (threadIdx.x < L1) { sl1b[threadIdx.x] = l1b[threadIdx.x]; sow[threadIdx.x] = ow[threadIdx.x]; }
    if (threadIdx.x == 0) sob = ob[0];
    __syncthreads();

    int t = blockIdx.x * blockDim.x + threadIdx.x;
    int i = t >> 1;            // node
    int a = t & 1;             // which 8-channel half
    float term = 0.0f;
    if (i < n) {
        int degc = __ldg(&g_degi[i]);
        float invdeg = 1.0f / (float)(degc + 1);    // + self loop
        uint4 r = *(const uint4*)&g_aggh[i * CC + a * 8];
        if (a == 0) g_degi[i] = 0;                  // reset for next graph replay
        float h[8];
        {
            const unsigned rr[4] = {r.x, r.y, r.z, r.w};
#pragma unroll
            for (int k = 0; k < 4; k++) {
                float2 f = __half22float2(*(const __half2*)&rr[k]);
                h[2 * k]     = f.x;
                h[2 * k + 1] = f.y;
            }
        }
        int cbase = a * 8;
#pragma unroll
        for (int k = 0; k < 8; k++)
            h[k] = fmaxf(fmaf(h[k], invdeg, sb[cbase + k]), 0.0f);

        float s[L1];
#pragma unroll
        for (int j = 0; j < L1; j++) {
            float acc = 0.0f;
#pragma unroll
            for (int k = 0; k < 8; k++)
                acc = fmaf(h[k], sl1w[(cbase + k) * L1 + j], acc);
            s[j] = acc;
        }
        float z = 0.0f;
#pragma unroll
        for (int j = 0; j < L1; j++) {
            float sj = s[j] + __shfl_xor_sync(0xFFFFFFFFu, s[j], 1);
            float h2 = fmaxf(sj + sl1b[j], 0.0f);
            z = fmaf(h2, sow[j], z);
        }
        if (a == 0) {
            z += sob;
            float p = 1.0f / (1.0f + __expf(-z));
            pout[i] = p;
            const float eps = 1e-7f;
            float pc = fminf(fmaxf(p, eps), 1.0f - eps);
            float sel = (labels[i] > 0.5f) ? pc : (1.0f - pc);  // labels exactly 0/1
            term = wts[i] * (-__logf(sel)) * inv_n;
        }
    }
    // block reduce
#pragma unroll
    for (int off = 16; off > 0; off >>= 1)
        term += __shfl_down_sync(0xFFFFFFFFu, term, off);
    __shared__ float wsum[8];
    int wid = threadIdx.x >> 5, lid = threadIdx.x & 31;
    if (lid == 0) wsum[wid] = term;
    __syncthreads();
    if (threadIdx.x == 0 && losss) {
        float sum = 0.0f;
#pragma unroll
        for (int k = 0; k < (int)(blockDim.x >> 5); k++) sum += wsum[k];
        atomicAdd(losss, sum);
    }
}

// ---------------- launch ----------------
extern "C" void kernel_launch(void* const* d_in, const int* in_sizes, int n_in,
                              void* d_out, int out_size) {
    const float* x      = (const float*)d_in[0];
    const void*  ei     = d_in[1];
    const float* labels = (const float*)d_in[2];
    const float* wts    = (const float*)d_in[3];
    const float* W      = (const float*)d_in[4];
    // d_in[5]=u, d_in[6]=c unused (H=1 softmax == 1)
    const float* bias   = (const float*)d_in[7];
    const float* l1w    = (const float*)d_in[8];
    const float* l1b    = (const float*)d_in[9];
    const float* ow     = (const float*)d_in[10];
    const float* ob     = (const float*)d_in[11];

    int n = in_sizes[0] / FF;
    int E = in_sizes[1] / 2;

    float* out = (float*)d_out;
    int loss_slot = (out_size == n + 1) ? 1 : 0;
    float* pout  = loss_slot ? (out + 1) : out;
    float* losss = loss_slot ? out : (float*)0;

    int projBlocks = (n + 15) / 16;
    int histBlocks = (E + 1023) / 1024;

    k_proj_hist<<<projBlocks + histBlocks, 256>>>(x, W, ei, losss, n, E, projBlocks);

    int Eq = (E + 3) / 4;
    long long threads = (long long)Eq * 2;
    k_edge<<<(int)((threads + 511) / 512), 512>>>(ei, E, Eq);

    k_head<<<(n * 2 + 255) / 256, 256>>>(bias, l1w, l1b, ow, ob, labels, wts,
                                         pout, losss, n, 1.0f / (float)n);
}